// round 14
// baseline (speedup 1.0000x reference)
#include <cuda_runtime.h>

// Problem constants (fixed by the dataset)
#define BB 32
#define LL 1024
#define HH 384
#define H4 (HH / 4)          // 96 float4 per row
#define MAX_DUR 8
#define T_MAX (LL * (MAX_DUR - 1))   // 7168, multiple of 4 -> int4-aligned rows
#define RPT 8                // rows per thread
#define TILE_T 32            // rows per block (4 y-slices * 8)

// Scratch (no cudaMalloc allowed).
__device__ __align__(16) int g_idx[BB * T_MAX];
__device__ int g_total[BB];
__device__ int g_ready[BB];   // ==128 when batch b's scan is published
__device__ int g_cnt[BB];     // finished-block counter per batch (self-reset)

// ---------------------------------------------------------------------------
// Single fused kernel. Grid: tpb*BB 1-D blocks, block (96,4)=384 threads.
//  - Blocks 0..31 first run the duration scan for batch==blockIdx.x and
//    publish g_idx/g_total, then release via fenced atomic count (128).
//  - Every block spin-waits on g_ready[its batch], then runs the R9 expand
//    body for its 32-row tile (8 rows/thread, dedup gathers, streaming st).
//  - Last block per batch resets g_ready/g_cnt -> deterministic per call.
// ---------------------------------------------------------------------------
__global__ void __launch_bounds__(384, 3)
lr_fused_kernel(const float* __restrict__ hid,
                const int* __restrict__ dur,
                float* __restrict__ out,
                float* __restrict__ mask,
                int T, int tpb) {
    const int lane = threadIdx.x;                 // 0..95
    const int ty = threadIdx.y;                   // 0..3
    const int tl = ty * H4 + lane;                // flat 0..383 (hw linear id)
    const int g = blockIdx.x;

    // ---- Phase A: scan duty for blocks 0..31 ----
    if (g < BB) {
        __shared__ int s_wpre[4];
        int dd0, dd1, dd2, dd3, dd4, dd5, dd6, dd7;
        int sum = 0, inc = 0;
        if (tl < 128) {
            const int4* dp = (const int4*)(dur + g * LL + tl * 8);
            int4 a0 = dp[0], a1 = dp[1];
            dd0 = a0.x; dd1 = a0.y; dd2 = a0.z; dd3 = a0.w;
            dd4 = a1.x; dd5 = a1.y; dd6 = a1.z; dd7 = a1.w;
            sum = dd0 + dd1 + dd2 + dd3 + dd4 + dd5 + dd6 + dd7;
            inc = sum;
            #pragma unroll
            for (int o = 1; o < 32; o <<= 1) {
                int y = __shfl_up_sync(0xFFFFFFFFu, inc, o);
                if ((tl & 31) >= o) inc += y;
            }
            if ((tl & 31) == 31) s_wpre[tl >> 5] = inc;
        }
        __syncthreads();
        if (tl < 128) {
            const int w = tl >> 5;
            int base = 0;
            if (w > 0) base += s_wpre[0];
            if (w > 1) base += s_wpre[1];
            if (w > 2) base += s_wpre[2];

            int run = base + inc - sum;   // exclusive prefix of my 8 elements
            int* __restrict__ idx_row = g_idx + g * T_MAX;
            const int j0 = tl * 8;
            int dd[8] = {dd0, dd1, dd2, dd3, dd4, dd5, dd6, dd7};
            #pragma unroll
            for (int k = 0; k < 8; k++) {
                const int e = run + dd[k];
                for (int t = run; t < e; t++) idx_row[t] = j0 + k;
                run = e;
            }
            if (tl == 127) g_total[g] = run;

            __threadfence();               // publish my stores device-wide
            atomicAdd(&g_ready[g], 1);     // release: count reaches 128
        }
    }

    // ---- Phase B: expand one 32-row tile ----
    const int b = g / tpb;
    const int t0 = (g - b * tpb) * TILE_T + ty * RPT;

    // acquire: wait for batch b's scan
    if (*(volatile int*)&g_ready[b] != 128) {
        while (*(volatile int*)&g_ready[b] != 128) __nanosleep(32);
    }
    __threadfence();

    if (t0 < T) {
        const int total = g_total[b];

        const int* __restrict__ idx_row = g_idx + b * T_MAX;
        int idx[RPT];
        *(int4*)(&idx[0]) = *(const int4*)(idx_row + t0);
        *(int4*)(&idx[4]) = *(const int4*)(idx_row + t0 + 4);

        const float4* __restrict__ src =
            (const float4*)(hid) + b * (LL * H4) + lane;
        const float4 z = make_float4(0.f, 0.f, 0.f, 0.f);

        // Front-batched gathers, skipping duplicates of the previous row.
        float4 v[RPT];
        #pragma unroll
        for (int k = 0; k < RPT; k++) {
            float4 vv = z;
            const bool live = (t0 + k < total);
            const bool dup = (k > 0) && (idx[k] == idx[k - 1]);
            if (live && !dup) vv = src[idx[k] * H4];
            v[k] = vv;
        }
        #pragma unroll
        for (int k = 1; k < RPT; k++) {
            if ((t0 + k < total) && (idx[k] == idx[k - 1])) v[k] = v[k - 1];
        }

        float4* __restrict__ dst =
            (float4*)(out) + (b * T + t0) * H4 + lane;

        if (t0 + RPT <= T) {
            #pragma unroll
            for (int k = 0; k < RPT; k++) __stcs(dst + k * H4, v[k]);

            if (lane == 0) {
                float4 m0, m1;
                m0.x = (t0 + 0 < total) ? 1.f : 0.f;
                m0.y = (t0 + 1 < total) ? 1.f : 0.f;
                m0.z = (t0 + 2 < total) ? 1.f : 0.f;
                m0.w = (t0 + 3 < total) ? 1.f : 0.f;
                m1.x = (t0 + 4 < total) ? 1.f : 0.f;
                m1.y = (t0 + 5 < total) ? 1.f : 0.f;
                m1.z = (t0 + 6 < total) ? 1.f : 0.f;
                m1.w = (t0 + 7 < total) ? 1.f : 0.f;
                float4* mp = (float4*)(mask + b * T + t0);
                __stcs(mp, m0);
                __stcs(mp + 1, m1);
            }
        } else {
            #pragma unroll
            for (int k = 0; k < RPT; k++) {
                if (t0 + k < T) {
                    __stcs(dst + k * H4, v[k]);
                    if (lane == 0)
                        mask[b * T + t0 + k] = (t0 + k < total) ? 1.f : 0.f;
                }
            }
        }
    }

    // ---- Self-reset for next graph replay (deterministic per call) ----
    __syncthreads();            // whole block done spinning/working
    if (tl == 0) {
        int old = atomicAdd(&g_cnt[b], 1);
        if (old == tpb - 1) {   // last block of batch b this call
            g_cnt[b] = 0;
            g_ready[b] = 0;
        }
    }
}

// ---------------------------------------------------------------------------
extern "C" void kernel_launch(void* const* d_in, const int* in_sizes, int n_in,
                              void* d_out, int out_size) {
    const float* hid = (const float*)d_in[0];   // (B, L, H) f32
    const int*   dur = (const int*)d_in[1];     // (B, L) i32

    // out_size = B*T*H + B*T = B*T*(H+1)
    const int T = out_size / (BB * (HH + 1));
    const long long n_rows = (long long)BB * T;

    float* out  = (float*)d_out;                // B*T*H
    float* mask = (float*)d_out + n_rows * HH;  // B*T

    const int tpb = (T + TILE_T - 1) / TILE_T;

    dim3 grid(tpb * BB);
    dim3 blk(H4, 4);
    lr_fused_kernel<<<grid, blk>>>(hid, dur, out, mask, T, tpb);
}

// round 15
// speedup vs baseline: 1.2810x; 1.2810x over previous
#include <cuda_runtime.h>

// Problem constants (fixed by the dataset)
#define BB 32
#define LL 1024
#define HH 384
#define H4 (HH / 4)          // 96 float4 per row
#define MAX_DUR 8
#define T_MAX (LL * (MAX_DUR - 1))   // 7168, multiple of 4 -> int4-aligned rows
#define RPT 8                // rows per thread
#define TILE_T 32            // rows per block (4 y-slices * 8)

// Scratch (no cudaMalloc allowed). Row stride is T_MAX so every int4 idx
// load is aligned regardless of runtime T.
__device__ __align__(16) int g_idx[BB * T_MAX];
__device__ int g_total[BB];

// ---------------------------------------------------------------------------
// Kernel 1: per-batch inclusive scan of durations; scatter source indices
// into SMEM (cheap scalar STS instead of scattered global stores), then
// coalesced int4 copy SMEM -> g_idx. Entries beyond total[b] are left
// uninitialized: the expand kernel only dereferences idx[t] when t < total.
// ---------------------------------------------------------------------------
__global__ void lr_scan_scatter_kernel(const int* __restrict__ dur, int T) {
    __shared__ __align__(16) int s_idx[T_MAX];   // 28 KB
    __shared__ int wsum[32];

    const int b = blockIdx.x;
    const int tid = threadIdx.x;            // 0..1023
    const int lane = tid & 31;
    const int wid = tid >> 5;

    const int d = dur[b * LL + tid];
    int x = d;

    #pragma unroll
    for (int o = 1; o < 32; o <<= 1) {
        int y = __shfl_up_sync(0xFFFFFFFFu, x, o);
        if (lane >= o) x += y;
    }

    if (lane == 31) wsum[wid] = x;
    __syncthreads();

    if (wid == 0) {
        int s = wsum[lane];
        #pragma unroll
        for (int o = 1; o < 32; o <<= 1) {
            int y = __shfl_up_sync(0xFFFFFFFFu, s, o);
            if (lane >= o) s += y;
        }
        wsum[lane] = s;
    }
    __syncthreads();

    if (wid > 0) x += wsum[wid - 1];        // inclusive cumsum at position tid

    // scatter into SMEM: frames [x-d, x) come from source row tid
    const int start = x - d;
    #pragma unroll
    for (int k = 0; k < MAX_DUR; k++) {
        if (k < d) s_idx[start + k] = tid;
    }

    if (tid == LL - 1) g_total[b] = x;
    __syncthreads();

    // coalesced copy SMEM -> global (int4); covers all tiles expand reads
    const int n4 = (T + TILE_T - 1) / TILE_T * (TILE_T / 4);  // tile-padded
    int4* __restrict__ dst = (int4*)(g_idx + b * T_MAX);
    const int4* __restrict__ srcv = (const int4*)s_idx;
    for (int i = tid; i < n4; i += LL) dst[i] = srcv[i];
}

// ---------------------------------------------------------------------------
// Kernel 2: expand (R9 champion, unchanged). 8 contiguous rows per thread,
// front-batched gathers with duplicate-source dedup, streaming stores.
// ---------------------------------------------------------------------------
__global__ void __launch_bounds__(384, 3)
lr_expand_kernel(const float* __restrict__ hid,
                 float* __restrict__ out,
                 float* __restrict__ mask,
                 int T) {
    const int lane = threadIdx.x;           // 0..95
    const int b = blockIdx.y;
    const int t0 = blockIdx.x * TILE_T + threadIdx.y * RPT;
    if (t0 >= T) return;

    const int total = g_total[b];

    // idx loads: always in-bounds and 16B-aligned (stride T_MAX, t0 % 8 == 0)
    const int* __restrict__ idx_row = g_idx + b * T_MAX;
    int idx[RPT];
    *(int4*)(&idx[0]) = *(const int4*)(idx_row + t0);
    *(int4*)(&idx[4]) = *(const int4*)(idx_row + t0 + 4);

    const float4* __restrict__ src =
        (const float4*)(hid) + (long long)b * LL * H4 + lane;
    const float4 z = make_float4(0.f, 0.f, 0.f, 0.f);

    // Front-batched gathers, skipping duplicates of the previous row.
    float4 v[RPT];
    #pragma unroll
    for (int k = 0; k < RPT; k++) {
        float4 vv = z;
        const bool live = (t0 + k < total);
        const bool dup = (k > 0) && (idx[k] == idx[k - 1]);
        if (live && !dup) vv = src[idx[k] * H4];
        v[k] = vv;
    }
    // Propagate duplicates (sequential, handles chains).
    #pragma unroll
    for (int k = 1; k < RPT; k++) {
        if ((t0 + k < total) && (idx[k] == idx[k - 1])) v[k] = v[k - 1];
    }

    float4* __restrict__ dst =
        (float4*)(out) + ((long long)b * T + t0) * H4 + lane;

    if (t0 + RPT <= T) {
        #pragma unroll
        for (int k = 0; k < RPT; k++) __stcs(dst + k * H4, v[k]);

        if (lane == 0) {
            float4 m0, m1;
            m0.x = (t0 + 0 < total) ? 1.f : 0.f;
            m0.y = (t0 + 1 < total) ? 1.f : 0.f;
            m0.z = (t0 + 2 < total) ? 1.f : 0.f;
            m0.w = (t0 + 3 < total) ? 1.f : 0.f;
            m1.x = (t0 + 4 < total) ? 1.f : 0.f;
            m1.y = (t0 + 5 < total) ? 1.f : 0.f;
            m1.z = (t0 + 6 < total) ? 1.f : 0.f;
            m1.w = (t0 + 7 < total) ? 1.f : 0.f;
            float4* mp = (float4*)(mask + (long long)b * T + t0);
            __stcs(mp, m0);
            __stcs(mp + 1, m1);
        }
    } else {
        // T-tail: per-row bounds
        #pragma unroll
        for (int k = 0; k < RPT; k++) {
            if (t0 + k < T) {
                __stcs(dst + k * H4, v[k]);
                if (lane == 0)
                    mask[(long long)b * T + t0 + k] = (t0 + k < total) ? 1.f : 0.f;
            }
        }
    }
}

// ---------------------------------------------------------------------------
extern "C" void kernel_launch(void* const* d_in, const int* in_sizes, int n_in,
                              void* d_out, int out_size) {
    const float* hid = (const float*)d_in[0];   // (B, L, H) f32
    const int*   dur = (const int*)d_in[1];     // (B, L) i32

    // out_size = B*T*H + B*T = B*T*(H+1)
    const int T = out_size / (BB * (HH + 1));
    const long long n_rows = (long long)BB * T;

    float* out  = (float*)d_out;                // B*T*H
    float* mask = (float*)d_out + n_rows * HH;  // B*T

    lr_scan_scatter_kernel<<<BB, LL>>>(dur, T);

    dim3 grid((T + TILE_T - 1) / TILE_T, BB);
    dim3 blk(H4, 4);
    lr_expand_kernel<<<grid, blk>>>(hid, out, mask, T);
}